// round 12
// baseline (speedup 1.0000x reference)
#include <cuda_runtime.h>

#define NN 100000
#define NE 600000
#define CIN 16
#define HW 48
#define NL 5
#define EB ((NE + 127) / 128)

typedef unsigned long long u64;

// ---- scratch (device globals: allocation-guard safe) ----
__device__ float  g_x1[NN * CIN];
__device__ float  g_x2[NN * CIN];
__device__ float  g_agg[NN * CIN];
__device__ float  g_cnt[NN];
__device__ float  g_ef1[(size_t)NE * HW];   // 115 MB intermediate edge features
__device__ double g_sl[2];

// ---- EdgeConv weights in the constant bank (uniform port, not LSU) ----
// layout (float offsets): W0@0(1536) B0@1536(48) WH@1584(11520) BH@13104(240)
//                         WC@13344(2352) BC@15696(48)   total 15744 f = 61.5KB
#define C_W0 0
#define C_B0 1536
#define C_WH 1584
#define C_BH 13104
#define C_WC 13344
#define C_BC 15696
__constant__ float c_ec[15744];

// ---- f32x2 helpers ----
__device__ __forceinline__ u64 fma2(u64 a, u64 b, u64 c) {
    u64 d;
    asm("fma.rn.f32x2 %0,%1,%2,%3;" : "=l"(d) : "l"(a), "l"(b), "l"(c));
    return d;
}
__device__ __forceinline__ u64 bcast2(float v) {
    u64 r;
    asm("mov.b64 %0,{%1,%1};" : "=l"(r) : "f"(v));
    return r;
}
union Q4 { float4 f4; u64 u[2]; };
union P2 { u64 u; float2 f; };

// ---------------------------------------------------------------------------
__global__ void zero_kernel(int phase) {
    int i = blockIdx.x * blockDim.x + threadIdx.x;
    if (i < NN * CIN) g_agg[i] = 0.f;
    if (i < NN)       g_cnt[i] = 0.f;
    if (phase == 0 && i < 2) g_sl[i] = 0.0;
}

// ---------------------------------------------------------------------------
// NodeConv message + scatter (f32x2-packed MLP: 16 outputs = 8 pair-accs).
__global__ __launch_bounds__(128) void nc_kernel(
    const float* __restrict__ x, const int* __restrict__ ei,
    const float* __restrict__ ang,
    const float* __restrict__ w0, const float* __restrict__ b0,
    const float* __restrict__ wh, const float* __restrict__ bh)
{
    __shared__ __align__(16) float sw0[33 * 16];
    __shared__ __align__(16) float sb0[16];
    __shared__ __align__(16) float swh[5 * 16 * 16];
    __shared__ __align__(16) float sbh[5 * 16];
    int t = threadIdx.x;
    for (int i = t; i < 33 * 16; i += 128) sw0[i] = w0[i];
    for (int i = t; i < 16;      i += 128) sb0[i] = b0[i];
    for (int i = t; i < 5 * 256; i += 128) swh[i] = wh[i];
    for (int i = t; i < 80;      i += 128) sbh[i] = bh[i];
    __syncthreads();

    int e = blockIdx.x * 128 + t;
    if (e >= NE) return;
    int s = ei[e];
    int d = ei[NE + e];

    float in[33];
    const float4* xd4 = (const float4*)(x + (size_t)d * CIN);
    const float4* xs4 = (const float4*)(x + (size_t)s * CIN);
    #pragma unroll
    for (int q = 0; q < 4; q++) {
        float4 v = xd4[q];
        in[q * 4 + 0] = v.x; in[q * 4 + 1] = v.y; in[q * 4 + 2] = v.z; in[q * 4 + 3] = v.w;
    }
    #pragma unroll
    for (int q = 0; q < 4; q++) {
        float4 v = xs4[q];
        in[16 + q * 4 + 0] = v.x; in[16 + q * 4 + 1] = v.y;
        in[16 + q * 4 + 2] = v.z; in[16 + q * 4 + 3] = v.w;
    }
    in[32] = ang[e];

    u64 acc[8];
    float h[16];
    #pragma unroll
    for (int jp = 0; jp < 8; jp++) acc[jp] = *(const u64*)(sb0 + 2 * jp);
    #pragma unroll
    for (int k = 0; k < 33; k++) {
        u64 vp = bcast2(in[k]);
        const float4* wr = (const float4*)(sw0 + k * 16);
        #pragma unroll
        for (int q = 0; q < 4; q++) {
            Q4 w; w.f4 = wr[q];
            acc[2 * q + 0] = fma2(vp, w.u[0], acc[2 * q + 0]);
            acc[2 * q + 1] = fma2(vp, w.u[1], acc[2 * q + 1]);
        }
    }
    #pragma unroll
    for (int jp = 0; jp < 8; jp++) {
        P2 p; p.u = acc[jp];
        h[2 * jp + 0] = fmaxf(p.f.x, 0.f);
        h[2 * jp + 1] = fmaxf(p.f.y, 0.f);
    }

    #pragma unroll 1
    for (int l = 0; l < NL; l++) {
        const float* wl = swh + l * 256;
        const float* bl = sbh + l * 16;
        #pragma unroll
        for (int jp = 0; jp < 8; jp++) acc[jp] = *(const u64*)(bl + 2 * jp);
        #pragma unroll
        for (int k = 0; k < 16; k++) {
            u64 vp = bcast2(h[k]);
            const float4* wr = (const float4*)(wl + k * 16);
            #pragma unroll
            for (int q = 0; q < 4; q++) {
                Q4 w; w.f4 = wr[q];
                acc[2 * q + 0] = fma2(vp, w.u[0], acc[2 * q + 0]);
                acc[2 * q + 1] = fma2(vp, w.u[1], acc[2 * q + 1]);
            }
        }
        #pragma unroll
        for (int jp = 0; jp < 8; jp++) {
            P2 p; p.u = acc[jp];
            h[2 * jp + 0] = fmaxf(p.f.x, 0.f);
            h[2 * jp + 1] = fmaxf(p.f.y, 0.f);
        }
    }

    #pragma unroll
    for (int j = 0; j < 16; j++) atomicAdd(&g_agg[(size_t)d * CIN + j], h[j]);
    atomicAdd(&g_cnt[d], 1.f);
}

// ---------------------------------------------------------------------------
__global__ void div_kernel(float* __restrict__ out) {
    int i = blockIdx.x * blockDim.x + threadIdx.x;
    if (i >= NN * CIN) return;
    float c = g_cnt[i / CIN];
    out[i] = g_agg[i] / fmaxf(c, 1.f);
}

// ---------------------------------------------------------------------------
// EdgeConv, f32x2-packed, both passes fused, WEIGHTS FROM THE CONSTANT BANK.
// All weight/bias reads are warp-uniform compile-time-offset loads -> LDCU
// (uniform port), freeing the LSU pipe for the input stash only.
// IS_EC1=1: combine [fe, action](49) -> 48, out = g_ef1
// IS_EC1=0: combine [fe, ef1](96)   -> 1,  out = d_out
template <int IS_EC1>
__global__ __launch_bounds__(128, 2) void ec_kernel(
    const float* __restrict__ x, const int* __restrict__ ei,
    const float* __restrict__ extra,
    float* __restrict__ out, int sli)
{
    __shared__ __align__(16) float stash[32 * 128];

    int t = threadIdx.x;
    int e = blockIdx.x * 128 + t;
    bool active = (e < NE);
    if (active) {
        int s = ei[e];
        int d = ei[NE + e];
        // stash = [xd(16), xs(16)]  (pass0 concat order; pass1 = index XOR 16)
        const float4* a4 = (const float4*)(x + (size_t)d * CIN);
        const float4* b4 = (const float4*)(x + (size_t)s * CIN);
        #pragma unroll
        for (int q = 0; q < 4; q++) {
            float4 v = a4[q];
            stash[(q * 4 + 0) * 128 + t] = v.x; stash[(q * 4 + 1) * 128 + t] = v.y;
            stash[(q * 4 + 2) * 128 + t] = v.z; stash[(q * 4 + 3) * 128 + t] = v.w;
        }
        #pragma unroll
        for (int q = 0; q < 4; q++) {
            float4 v = b4[q];
            stash[(16 + q * 4 + 0) * 128 + t] = v.x; stash[(16 + q * 4 + 1) * 128 + t] = v.y;
            stash[(16 + q * 4 + 2) * 128 + t] = v.z; stash[(16 + q * 4 + 3) * 128 + t] = v.w;
        }
    }
    __syncthreads();

    float sq = 0.f;
    if (active) {
        float h0[48], h1[48];
        u64 acc0[24], acc1[24];

        // ---- layer 0: 32 -> 48, both passes share every weight quad ----
        #pragma unroll
        for (int jp = 0; jp < 24; jp++) {
            u64 b = *(const u64*)(c_ec + C_B0 + 2 * jp);
            acc0[jp] = b; acc1[jp] = b;
        }
        #pragma unroll
        for (int k = 0; k < 32; k++) {
            u64 p0 = bcast2(stash[k * 128 + t]);
            u64 p1 = bcast2(stash[(k ^ 16) * 128 + t]);
            const float4* wr = (const float4*)(c_ec + C_W0 + k * 48);
            #pragma unroll
            for (int q = 0; q < 12; q++) {
                Q4 w; w.f4 = wr[q];
                acc0[2 * q + 0] = fma2(p0, w.u[0], acc0[2 * q + 0]);
                acc0[2 * q + 1] = fma2(p0, w.u[1], acc0[2 * q + 1]);
                acc1[2 * q + 0] = fma2(p1, w.u[0], acc1[2 * q + 0]);
                acc1[2 * q + 1] = fma2(p1, w.u[1], acc1[2 * q + 1]);
            }
        }
        #pragma unroll
        for (int jp = 0; jp < 24; jp++) {
            P2 p; p.u = acc0[jp];
            h0[2 * jp + 0] = fmaxf(p.f.x, 0.f);
            h0[2 * jp + 1] = fmaxf(p.f.y, 0.f);
            P2 r; r.u = acc1[jp];
            h1[2 * jp + 0] = fmaxf(r.f.x, 0.f);
            h1[2 * jp + 1] = fmaxf(r.f.y, 0.f);
        }

        // ---- hidden layers: 48 -> 48, x5, fused passes ----
        #pragma unroll 1
        for (int l = 0; l < NL; l++) {
            const float* wl = c_ec + C_WH + l * 2304;
            const float* bl = c_ec + C_BH + l * 48;
            #pragma unroll
            for (int jp = 0; jp < 24; jp++) {
                u64 b = *(const u64*)(bl + 2 * jp);
                acc0[jp] = b; acc1[jp] = b;
            }
            #pragma unroll
            for (int k = 0; k < 48; k++) {
                u64 p0 = bcast2(h0[k]);
                u64 p1 = bcast2(h1[k]);
                const float4* wr = (const float4*)(wl + k * 48);
                #pragma unroll
                for (int q = 0; q < 12; q++) {
                    Q4 w; w.f4 = wr[q];
                    acc0[2 * q + 0] = fma2(p0, w.u[0], acc0[2 * q + 0]);
                    acc0[2 * q + 1] = fma2(p0, w.u[1], acc0[2 * q + 1]);
                    acc1[2 * q + 0] = fma2(p1, w.u[0], acc1[2 * q + 0]);
                    acc1[2 * q + 1] = fma2(p1, w.u[1], acc1[2 * q + 1]);
                }
            }
            #pragma unroll
            for (int jp = 0; jp < 24; jp++) {
                P2 p; p.u = acc0[jp];
                h0[2 * jp + 0] = fmaxf(p.f.x, 0.f);
                h0[2 * jp + 1] = fmaxf(p.f.y, 0.f);
                P2 r; r.u = acc1[jp];
                h1[2 * jp + 0] = fmaxf(r.f.x, 0.f);
                h1[2 * jp + 1] = fmaxf(r.f.y, 0.f);
            }
        }

        // ---- side loss + fe (fe overwrites h0) ----
        #pragma unroll
        for (int j = 0; j < 48; j++) {
            float dl = h0[j] - h1[j];
            sq += dl * dl;
            h0[j] = 0.5f * (h0[j] + h1[j]);
        }

        if (IS_EC1) {
            float aact = extra[e];
            u64 o[24];
            #pragma unroll
            for (int jp = 0; jp < 24; jp++) o[jp] = *(const u64*)(c_ec + C_BC + 2 * jp);
            {   // action row (row 48)
                u64 ap = bcast2(aact);
                const float4* wr = (const float4*)(c_ec + C_WC + 48 * 48);
                #pragma unroll
                for (int q = 0; q < 12; q++) {
                    Q4 w; w.f4 = wr[q];
                    o[2 * q + 0] = fma2(ap, w.u[0], o[2 * q + 0]);
                    o[2 * q + 1] = fma2(ap, w.u[1], o[2 * q + 1]);
                }
            }
            #pragma unroll
            for (int k = 0; k < 48; k++) {
                u64 vp = bcast2(h0[k]);
                const float4* wr = (const float4*)(c_ec + C_WC + k * 48);
                #pragma unroll
                for (int q = 0; q < 12; q++) {
                    Q4 w; w.f4 = wr[q];
                    o[2 * q + 0] = fma2(vp, w.u[0], o[2 * q + 0]);
                    o[2 * q + 1] = fma2(vp, w.u[1], o[2 * q + 1]);
                }
            }
            #pragma unroll
            for (int q = 0; q < 12; q++) {
                P2 p0; p0.u = o[2 * q + 0];
                P2 p1; p1.u = o[2 * q + 1];
                *(float4*)(out + (size_t)e * 48 + q * 4) =
                    make_float4(p0.f.x, p0.f.y, p1.f.x, p1.f.y);
            }
        } else {
            float o = c_ec[C_BC];
            #pragma unroll
            for (int k = 0; k < 48; k++) o += h0[k] * c_ec[C_WC + k];
            const float4* ef = (const float4*)(extra + (size_t)e * 48);
            #pragma unroll
            for (int q = 0; q < 12; q++) {
                float4 v = ef[q];
                o += v.x * c_ec[C_WC + 48 + q * 4 + 0];
                o += v.y * c_ec[C_WC + 48 + q * 4 + 1];
                o += v.z * c_ec[C_WC + 48 + q * 4 + 2];
                o += v.w * c_ec[C_WC + 48 + q * 4 + 3];
            }
            out[e] = o;
        }
    }

    // side-loss reduction: warp shfl -> double atomic
    #pragma unroll
    for (int off = 16; off; off >>= 1)
        sq += __shfl_xor_sync(0xffffffffu, sq, off);
    if ((t & 31) == 0)
        atomicAdd(&g_sl[sli], (double)sq);
}

// ---------------------------------------------------------------------------
__global__ void fin_kernel(float* __restrict__ out) {
    double inv = 1.0 / ((double)NE * 48.0);
    out[NE] = (float)(0.5 * (g_sl[0] * inv + g_sl[1] * inv));
}

// ---------------------------------------------------------------------------
static void fill_const(const float* w0, const float* b0, const float* wh,
                       const float* bh, const float* wc, const float* bc,
                       int wcN, int bcN)
{
    cudaMemcpyToSymbolAsync(c_ec, w0, 1536 * 4,  (size_t)C_W0 * 4, cudaMemcpyDeviceToDevice);
    cudaMemcpyToSymbolAsync(c_ec, b0, 48 * 4,    (size_t)C_B0 * 4, cudaMemcpyDeviceToDevice);
    cudaMemcpyToSymbolAsync(c_ec, wh, 11520 * 4, (size_t)C_WH * 4, cudaMemcpyDeviceToDevice);
    cudaMemcpyToSymbolAsync(c_ec, bh, 240 * 4,   (size_t)C_BH * 4, cudaMemcpyDeviceToDevice);
    cudaMemcpyToSymbolAsync(c_ec, wc, (size_t)wcN * 4, (size_t)C_WC * 4, cudaMemcpyDeviceToDevice);
    cudaMemcpyToSymbolAsync(c_ec, bc, (size_t)bcN * 4, (size_t)C_BC * 4, cudaMemcpyDeviceToDevice);
}

extern "C" void kernel_launch(void* const* d_in, const int* in_sizes, int n_in,
                              void* d_out, int out_size)
{
    const float* nf   = (const float*)d_in[0];
    const int*   ei   = (const int*)d_in[1];
    const float* ang  = (const float*)d_in[2];
    const float* act  = (const float*)d_in[4];
    const float* n1w0 = (const float*)d_in[5],  *n1b0 = (const float*)d_in[6];
    const float* n1wh = (const float*)d_in[7],  *n1bh = (const float*)d_in[8];
    const float* n2w0 = (const float*)d_in[9],  *n2b0 = (const float*)d_in[10];
    const float* n2wh = (const float*)d_in[11], *n2bh = (const float*)d_in[12];
    const float* e1w0 = (const float*)d_in[13], *e1b0 = (const float*)d_in[14];
    const float* e1wh = (const float*)d_in[15], *e1bh = (const float*)d_in[16];
    const float* e1wc = (const float*)d_in[17], *e1bc = (const float*)d_in[18];
    const float* e2w0 = (const float*)d_in[19], *e2b0 = (const float*)d_in[20];
    const float* e2wh = (const float*)d_in[21], *e2bh = (const float*)d_in[22];
    const float* e2wc = (const float*)d_in[23], *e2bc = (const float*)d_in[24];
    float* out = (float*)d_out;

    void *px1, *px2, *pef1;
    cudaGetSymbolAddress(&px1, g_x1);
    cudaGetSymbolAddress(&px2, g_x2);
    cudaGetSymbolAddress(&pef1, g_ef1);

    // NodeConv1 -> x1
    zero_kernel<<<6250, 256>>>(0);
    nc_kernel<<<EB, 128>>>(nf, ei, ang, n1w0, n1b0, n1wh, n1bh);
    div_kernel<<<6250, 256>>>((float*)px1);
    // EdgeConv1 -> ef1 (E x 48), sl[0]
    fill_const(e1w0, e1b0, e1wh, e1bh, e1wc, e1bc, 49 * 48, 48);
    ec_kernel<1><<<EB, 128>>>((const float*)px1, ei, act, (float*)pef1, 0);
    // NodeConv2 -> x2
    zero_kernel<<<6250, 256>>>(1);
    nc_kernel<<<EB, 128>>>((const float*)px1, ei, ang, n2w0, n2b0, n2wh, n2bh);
    div_kernel<<<6250, 256>>>((float*)px2);
    // EdgeConv2 -> out (E x 1), sl[1]
    fill_const(e2w0, e2b0, e2wh, e2bh, e2wc, e2bc, 96, 1);
    ec_kernel<0><<<EB, 128>>>((const float*)px2, ei, (const float*)pef1, out, 1);
    if (out_size > NE) fin_kernel<<<1, 1>>>(out);
}

// round 13
// speedup vs baseline: 1.4121x; 1.4121x over previous
#include <cuda_runtime.h>

#define NN 100000
#define NE 600000
#define CIN 16
#define HW 48
#define NL 5
#define EB ((NE + 127) / 128)

typedef unsigned long long u64;

// ---- scratch (device globals: allocation-guard safe) ----
__device__ float  g_x1[NN * CIN];
__device__ float  g_x2[NN * CIN];
__device__ float  g_agg[NN * CIN];
__device__ float  g_cnt[NN];
__device__ float  g_ef1[(size_t)NE * HW];   // 115 MB intermediate edge features
__device__ double g_sl[2];

// ---- EdgeConv weights ALSO in the constant bank (second read port) ----
// layout (float offsets): W0@0(1536) B0@1536(48) WH@1584(11520) BH@13104(240)
//                         WC@13344(2352) BC@15696(48)   total 15744 f = 61.5KB
#define C_W0 0
#define C_B0 1536
#define C_WH 1584
#define C_BH 13104
#define C_WC 13344
#define C_BC 15696
__constant__ float c_ec[15744];

// ---- f32x2 helpers ----
__device__ __forceinline__ u64 fma2(u64 a, u64 b, u64 c) {
    u64 d;
    asm("fma.rn.f32x2 %0,%1,%2,%3;" : "=l"(d) : "l"(a), "l"(b), "l"(c));
    return d;
}
__device__ __forceinline__ u64 bcast2(float v) {
    u64 r;
    asm("mov.b64 %0,{%1,%1};" : "=l"(r) : "f"(v));
    return r;
}
union Q4 { float4 f4; u64 u[2]; };
union P2 { u64 u; float2 f; };

// ---------------------------------------------------------------------------
__global__ void zero_kernel(int phase) {
    int i = blockIdx.x * blockDim.x + threadIdx.x;
    if (i < NN * CIN) g_agg[i] = 0.f;
    if (i < NN)       g_cnt[i] = 0.f;
    if (phase == 0 && i < 2) g_sl[i] = 0.0;
}

// ---------------------------------------------------------------------------
// NodeConv message + scatter (f32x2-packed MLP: 16 outputs = 8 pair-accs).
__global__ __launch_bounds__(128) void nc_kernel(
    const float* __restrict__ x, const int* __restrict__ ei,
    const float* __restrict__ ang,
    const float* __restrict__ w0, const float* __restrict__ b0,
    const float* __restrict__ wh, const float* __restrict__ bh)
{
    __shared__ __align__(16) float sw0[33 * 16];
    __shared__ __align__(16) float sb0[16];
    __shared__ __align__(16) float swh[5 * 16 * 16];
    __shared__ __align__(16) float sbh[5 * 16];
    int t = threadIdx.x;
    for (int i = t; i < 33 * 16; i += 128) sw0[i] = w0[i];
    for (int i = t; i < 16;      i += 128) sb0[i] = b0[i];
    for (int i = t; i < 5 * 256; i += 128) swh[i] = wh[i];
    for (int i = t; i < 80;      i += 128) sbh[i] = bh[i];
    __syncthreads();

    int e = blockIdx.x * 128 + t;
    if (e >= NE) return;
    int s = ei[e];
    int d = ei[NE + e];

    float in[33];
    const float4* xd4 = (const float4*)(x + (size_t)d * CIN);
    const float4* xs4 = (const float4*)(x + (size_t)s * CIN);
    #pragma unroll
    for (int q = 0; q < 4; q++) {
        float4 v = xd4[q];
        in[q * 4 + 0] = v.x; in[q * 4 + 1] = v.y; in[q * 4 + 2] = v.z; in[q * 4 + 3] = v.w;
    }
    #pragma unroll
    for (int q = 0; q < 4; q++) {
        float4 v = xs4[q];
        in[16 + q * 4 + 0] = v.x; in[16 + q * 4 + 1] = v.y;
        in[16 + q * 4 + 2] = v.z; in[16 + q * 4 + 3] = v.w;
    }
    in[32] = ang[e];

    u64 acc[8];
    float h[16];
    #pragma unroll
    for (int jp = 0; jp < 8; jp++) acc[jp] = *(const u64*)(sb0 + 2 * jp);
    #pragma unroll
    for (int k = 0; k < 33; k++) {
        u64 vp = bcast2(in[k]);
        const float4* wr = (const float4*)(sw0 + k * 16);
        #pragma unroll
        for (int q = 0; q < 4; q++) {
            Q4 w; w.f4 = wr[q];
            acc[2 * q + 0] = fma2(vp, w.u[0], acc[2 * q + 0]);
            acc[2 * q + 1] = fma2(vp, w.u[1], acc[2 * q + 1]);
        }
    }
    #pragma unroll
    for (int jp = 0; jp < 8; jp++) {
        P2 p; p.u = acc[jp];
        h[2 * jp + 0] = fmaxf(p.f.x, 0.f);
        h[2 * jp + 1] = fmaxf(p.f.y, 0.f);
    }

    #pragma unroll 1
    for (int l = 0; l < NL; l++) {
        const float* wl = swh + l * 256;
        const float* bl = sbh + l * 16;
        #pragma unroll
        for (int jp = 0; jp < 8; jp++) acc[jp] = *(const u64*)(bl + 2 * jp);
        #pragma unroll
        for (int k = 0; k < 16; k++) {
            u64 vp = bcast2(h[k]);
            const float4* wr = (const float4*)(wl + k * 16);
            #pragma unroll
            for (int q = 0; q < 4; q++) {
                Q4 w; w.f4 = wr[q];
                acc[2 * q + 0] = fma2(vp, w.u[0], acc[2 * q + 0]);
                acc[2 * q + 1] = fma2(vp, w.u[1], acc[2 * q + 1]);
            }
        }
        #pragma unroll
        for (int jp = 0; jp < 8; jp++) {
            P2 p; p.u = acc[jp];
            h[2 * jp + 0] = fmaxf(p.f.x, 0.f);
            h[2 * jp + 1] = fmaxf(p.f.y, 0.f);
        }
    }

    #pragma unroll
    for (int j = 0; j < 16; j++) atomicAdd(&g_agg[(size_t)d * CIN + j], h[j]);
    atomicAdd(&g_cnt[d], 1.f);
}

// ---------------------------------------------------------------------------
__global__ void div_kernel(float* __restrict__ out) {
    int i = blockIdx.x * blockDim.x + threadIdx.x;
    if (i >= NN * CIN) return;
    float c = g_cnt[i / CIN];
    out[i] = g_agg[i] / fmaxf(c, 1.f);
}

// ---------------------------------------------------------------------------
// EdgeConv, f32x2-packed, both passes fused. Weight quads are split between
// the SHARED port (q=0..7, LDS.128) and the CONSTANT port (q=8..11, LDC.128)
// so the two read pipes run concurrently and FFMA2 issue becomes the floor.
// IS_EC1=1: combine [fe, action](49) -> 48, out = g_ef1
// IS_EC1=0: combine [fe, ef1](96)   -> 1,  out = d_out
template <int IS_EC1>
__global__ __launch_bounds__(128, 2) void ec_kernel(
    const float* __restrict__ x, const int* __restrict__ ei,
    const float* __restrict__ extra,
    const float* __restrict__ w0, const float* __restrict__ b0,
    const float* __restrict__ wh, const float* __restrict__ bh,
    const float* __restrict__ wc, const float* __restrict__ bc,
    float* __restrict__ out, int sli)
{
    extern __shared__ float smem[];
    const int WC = IS_EC1 ? 49 * 48 : 96;
    const int BC = IS_EC1 ? 48 : 1;
    const int BCPAD = IS_EC1 ? 48 : 16;
    float* sw0   = smem;                   // 1536   (16B aligned)
    float* sb0   = sw0 + 1536;             // 48
    float* swh   = sb0 + 48;               // 11520
    float* sbh   = swh + 11520;            // 240
    float* swc   = sbh + 240;              // WC
    float* sbc   = swc + WC;               // BCPAD
    float* stash = sbc + BCPAD;            // 32*128 per-thread input slots

    int t = threadIdx.x;
    for (int i = t; i < 1536;  i += 128) sw0[i] = w0[i];
    for (int i = t; i < 48;    i += 128) sb0[i] = b0[i];
    for (int i = t; i < 11520; i += 128) swh[i] = wh[i];
    for (int i = t; i < 240;   i += 128) sbh[i] = bh[i];
    for (int i = t; i < WC;    i += 128) swc[i] = wc[i];
    for (int i = t; i < BC;    i += 128) sbc[i] = bc[i];

    int e = blockIdx.x * 128 + t;
    bool active = (e < NE);
    if (active) {
        int s = ei[e];
        int d = ei[NE + e];
        // stash = [xd(16), xs(16)]  (pass0 concat order; pass1 = index XOR 16)
        const float4* a4 = (const float4*)(x + (size_t)d * CIN);
        const float4* b4 = (const float4*)(x + (size_t)s * CIN);
        #pragma unroll
        for (int q = 0; q < 4; q++) {
            float4 v = a4[q];
            stash[(q * 4 + 0) * 128 + t] = v.x; stash[(q * 4 + 1) * 128 + t] = v.y;
            stash[(q * 4 + 2) * 128 + t] = v.z; stash[(q * 4 + 3) * 128 + t] = v.w;
        }
        #pragma unroll
        for (int q = 0; q < 4; q++) {
            float4 v = b4[q];
            stash[(16 + q * 4 + 0) * 128 + t] = v.x; stash[(16 + q * 4 + 1) * 128 + t] = v.y;
            stash[(16 + q * 4 + 2) * 128 + t] = v.z; stash[(16 + q * 4 + 3) * 128 + t] = v.w;
        }
    }
    __syncthreads();

    float sq = 0.f;
    if (active) {
        float h0[48], h1[48];
        u64 acc0[24], acc1[24];

        // ---- layer 0: 32 -> 48, fused passes, hybrid weight ports ----
        #pragma unroll
        for (int jp = 0; jp < 24; jp++) {
            u64 b = *(const u64*)(sb0 + 2 * jp);
            acc0[jp] = b; acc1[jp] = b;
        }
        #pragma unroll
        for (int k = 0; k < 32; k++) {
            u64 p0 = bcast2(stash[k * 128 + t]);
            u64 p1 = bcast2(stash[(k ^ 16) * 128 + t]);
            const float4* wr_s = (const float4*)(sw0 + k * 48);
            const float4* wr_c = (const float4*)(c_ec + C_W0 + k * 48);
            #pragma unroll
            for (int q = 0; q < 12; q++) {
                Q4 w; w.f4 = (q < 8) ? wr_s[q] : wr_c[q];
                acc0[2 * q + 0] = fma2(p0, w.u[0], acc0[2 * q + 0]);
                acc0[2 * q + 1] = fma2(p0, w.u[1], acc0[2 * q + 1]);
                acc1[2 * q + 0] = fma2(p1, w.u[0], acc1[2 * q + 0]);
                acc1[2 * q + 1] = fma2(p1, w.u[1], acc1[2 * q + 1]);
            }
        }
        #pragma unroll
        for (int jp = 0; jp < 24; jp++) {
            P2 p; p.u = acc0[jp];
            h0[2 * jp + 0] = fmaxf(p.f.x, 0.f);
            h0[2 * jp + 1] = fmaxf(p.f.y, 0.f);
            P2 r; r.u = acc1[jp];
            h1[2 * jp + 0] = fmaxf(r.f.x, 0.f);
            h1[2 * jp + 1] = fmaxf(r.f.y, 0.f);
        }

        // ---- hidden layers: 48 -> 48, x5, fused passes, hybrid ports ----
        #pragma unroll 1
        for (int l = 0; l < NL; l++) {
            const float* wl_s = swh + l * 2304;
            const float* wl_c = c_ec + C_WH + l * 2304;
            const float* bl   = sbh + l * 48;
            #pragma unroll
            for (int jp = 0; jp < 24; jp++) {
                u64 b = *(const u64*)(bl + 2 * jp);
                acc0[jp] = b; acc1[jp] = b;
            }
            #pragma unroll
            for (int k = 0; k < 48; k++) {
                u64 p0 = bcast2(h0[k]);
                u64 p1 = bcast2(h1[k]);
                const float4* wr_s = (const float4*)(wl_s + k * 48);
                const float4* wr_c = (const float4*)(wl_c + k * 48);
                #pragma unroll
                for (int q = 0; q < 12; q++) {
                    Q4 w; w.f4 = (q < 8) ? wr_s[q] : wr_c[q];
                    acc0[2 * q + 0] = fma2(p0, w.u[0], acc0[2 * q + 0]);
                    acc0[2 * q + 1] = fma2(p0, w.u[1], acc0[2 * q + 1]);
                    acc1[2 * q + 0] = fma2(p1, w.u[0], acc1[2 * q + 0]);
                    acc1[2 * q + 1] = fma2(p1, w.u[1], acc1[2 * q + 1]);
                }
            }
            #pragma unroll
            for (int jp = 0; jp < 24; jp++) {
                P2 p; p.u = acc0[jp];
                h0[2 * jp + 0] = fmaxf(p.f.x, 0.f);
                h0[2 * jp + 1] = fmaxf(p.f.y, 0.f);
                P2 r; r.u = acc1[jp];
                h1[2 * jp + 0] = fmaxf(r.f.x, 0.f);
                h1[2 * jp + 1] = fmaxf(r.f.y, 0.f);
            }
        }

        // ---- side loss + fe (fe overwrites h0) ----
        #pragma unroll
        for (int j = 0; j < 48; j++) {
            float dl = h0[j] - h1[j];
            sq += dl * dl;
            h0[j] = 0.5f * (h0[j] + h1[j]);
        }

        if (IS_EC1) {
            float aact = extra[e];
            u64 o[24];
            #pragma unroll
            for (int jp = 0; jp < 24; jp++) o[jp] = *(const u64*)(sbc + 2 * jp);
            {   // action row (row 48)
                u64 ap = bcast2(aact);
                const float4* wr = (const float4*)(swc + 48 * 48);
                #pragma unroll
                for (int q = 0; q < 12; q++) {
                    Q4 w; w.f4 = wr[q];
                    o[2 * q + 0] = fma2(ap, w.u[0], o[2 * q + 0]);
                    o[2 * q + 1] = fma2(ap, w.u[1], o[2 * q + 1]);
                }
            }
            #pragma unroll
            for (int k = 0; k < 48; k++) {
                u64 vp = bcast2(h0[k]);
                const float4* wr_s = (const float4*)(swc + k * 48);
                const float4* wr_c = (const float4*)(c_ec + C_WC + k * 48);
                #pragma unroll
                for (int q = 0; q < 12; q++) {
                    Q4 w; w.f4 = (q < 8) ? wr_s[q] : wr_c[q];
                    o[2 * q + 0] = fma2(vp, w.u[0], o[2 * q + 0]);
                    o[2 * q + 1] = fma2(vp, w.u[1], o[2 * q + 1]);
                }
            }
            #pragma unroll
            for (int q = 0; q < 12; q++) {
                P2 p0; p0.u = o[2 * q + 0];
                P2 p1; p1.u = o[2 * q + 1];
                *(float4*)(out + (size_t)e * 48 + q * 4) =
                    make_float4(p0.f.x, p0.f.y, p1.f.x, p1.f.y);
            }
        } else {
            float o = sbc[0];
            #pragma unroll
            for (int k = 0; k < 48; k++) o += h0[k] * swc[k];
            const float4* ef = (const float4*)(extra + (size_t)e * 48);
            #pragma unroll
            for (int q = 0; q < 12; q++) {
                float4 v = ef[q];
                o += v.x * swc[48 + q * 4 + 0];
                o += v.y * swc[48 + q * 4 + 1];
                o += v.z * swc[48 + q * 4 + 2];
                o += v.w * swc[48 + q * 4 + 3];
            }
            out[e] = o;
        }
    }

    // side-loss reduction: warp shfl -> double atomic
    #pragma unroll
    for (int off = 16; off; off >>= 1)
        sq += __shfl_xor_sync(0xffffffffu, sq, off);
    if ((t & 31) == 0)
        atomicAdd(&g_sl[sli], (double)sq);
}

// ---------------------------------------------------------------------------
__global__ void fin_kernel(float* __restrict__ out) {
    double inv = 1.0 / ((double)NE * 48.0);
    out[NE] = (float)(0.5 * (g_sl[0] * inv + g_sl[1] * inv));
}

// ---------------------------------------------------------------------------
static void fill_const(const float* w0, const float* wh, const float* wc, int wcN)
{
    cudaMemcpyToSymbolAsync(c_ec, w0, 1536 * 4,  (size_t)C_W0 * 4, cudaMemcpyDeviceToDevice);
    cudaMemcpyToSymbolAsync(c_ec, wh, 11520 * 4, (size_t)C_WH * 4, cudaMemcpyDeviceToDevice);
    cudaMemcpyToSymbolAsync(c_ec, wc, (size_t)wcN * 4, (size_t)C_WC * 4, cudaMemcpyDeviceToDevice);
}

extern "C" void kernel_launch(void* const* d_in, const int* in_sizes, int n_in,
                              void* d_out, int out_size)
{
    const float* nf   = (const float*)d_in[0];
    const int*   ei   = (const int*)d_in[1];
    const float* ang  = (const float*)d_in[2];
    const float* act  = (const float*)d_in[4];
    const float* n1w0 = (const float*)d_in[5],  *n1b0 = (const float*)d_in[6];
    const float* n1wh = (const float*)d_in[7],  *n1bh = (const float*)d_in[8];
    const float* n2w0 = (const float*)d_in[9],  *n2b0 = (const float*)d_in[10];
    const float* n2wh = (const float*)d_in[11], *n2bh = (const float*)d_in[12];
    const float* e1w0 = (const float*)d_in[13], *e1b0 = (const float*)d_in[14];
    const float* e1wh = (const float*)d_in[15], *e1bh = (const float*)d_in[16];
    const float* e1wc = (const float*)d_in[17], *e1bc = (const float*)d_in[18];
    const float* e2w0 = (const float*)d_in[19], *e2b0 = (const float*)d_in[20];
    const float* e2wh = (const float*)d_in[21], *e2bh = (const float*)d_in[22];
    const float* e2wc = (const float*)d_in[23], *e2bc = (const float*)d_in[24];
    float* out = (float*)d_out;

    void *px1, *px2, *pef1;
    cudaGetSymbolAddress(&px1, g_x1);
    cudaGetSymbolAddress(&px2, g_x2);
    cudaGetSymbolAddress(&pef1, g_ef1);

    size_t sh1 = (size_t)(1536 + 48 + 11520 + 240 + 49 * 48 + 48 + 32 * 128) * sizeof(float);
    size_t sh2 = (size_t)(1536 + 48 + 11520 + 240 + 96 + 16 + 32 * 128) * sizeof(float);
    cudaFuncSetAttribute(ec_kernel<1>, cudaFuncAttributeMaxDynamicSharedMemorySize, (int)sh1);
    cudaFuncSetAttribute(ec_kernel<0>, cudaFuncAttributeMaxDynamicSharedMemorySize, (int)sh2);
    cudaFuncSetAttribute(ec_kernel<1>, cudaFuncAttributePreferredSharedMemoryCarveout, 100);
    cudaFuncSetAttribute(ec_kernel<0>, cudaFuncAttributePreferredSharedMemoryCarveout, 100);

    // NodeConv1 -> x1
    zero_kernel<<<6250, 256>>>(0);
    nc_kernel<<<EB, 128>>>(nf, ei, ang, n1w0, n1b0, n1wh, n1bh);
    div_kernel<<<6250, 256>>>((float*)px1);
    // EdgeConv1 -> ef1 (E x 48), sl[0]
    fill_const(e1w0, e1wh, e1wc, 49 * 48);
    ec_kernel<1><<<EB, 128, sh1>>>((const float*)px1, ei, act,
                                   e1w0, e1b0, e1wh, e1bh, e1wc, e1bc,
                                   (float*)pef1, 0);
    // NodeConv2 -> x2
    zero_kernel<<<6250, 256>>>(1);
    nc_kernel<<<EB, 128>>>((const float*)px1, ei, ang, n2w0, n2b0, n2wh, n2bh);
    div_kernel<<<6250, 256>>>((float*)px2);
    // EdgeConv2 -> out (E x 1), sl[1]
    fill_const(e2w0, e2wh, e2wc, 96);
    ec_kernel<0><<<EB, 128, sh2>>>((const float*)px2, ei, (const float*)pef1,
                                   e2w0, e2b0, e2wh, e2bh, e2wc, e2bc,
                                   out, 1);
    if (out_size > NE) fin_kernel<<<1, 1>>>(out);
}

// round 14
// speedup vs baseline: 1.6445x; 1.1645x over previous
#include <cuda_runtime.h>

#define NN 100000
#define NE 600000
#define CIN 16
#define HW 48
#define NL 5
#define EB ((NE + 127) / 128)

typedef unsigned long long u64;

// ---- scratch (device globals: allocation-guard safe) ----
__device__ float  g_x1[NN * CIN];
__device__ float  g_x2[NN * CIN];
__device__ float  g_agg[NN * CIN];
__device__ float  g_cnt[NN];
__device__ float  g_ef1[(size_t)NE * HW];   // 115 MB intermediate edge features
__device__ double g_sl[2];

// ---- EdgeConv biases in the constant bank (tiny: 288 floats) ----
#define C_B0 0
#define C_BH 48
__constant__ __align__(16) float c_ec[288];

// ---- f32x2 helpers ----
__device__ __forceinline__ u64 fma2(u64 a, u64 b, u64 c) {
    u64 d;
    asm("fma.rn.f32x2 %0,%1,%2,%3;" : "=l"(d) : "l"(a), "l"(b), "l"(c));
    return d;
}
__device__ __forceinline__ u64 bcast2(float v) {
    u64 r;
    asm("mov.b64 %0,{%1,%1};" : "=l"(r) : "f"(v));
    return r;
}
union Q4 { float4 f4; u64 u[2]; };
union P2 { u64 u; float2 f; };

// ---------------------------------------------------------------------------
__global__ void zero_kernel(int phase) {
    int i = blockIdx.x * blockDim.x + threadIdx.x;
    if (i < NN * CIN) g_agg[i] = 0.f;
    if (i < NN)       g_cnt[i] = 0.f;
    if (phase == 0 && i < 2) g_sl[i] = 0.0;
}

// ---------------------------------------------------------------------------
// NodeConv message + scatter (f32x2-packed MLP: 16 outputs = 8 pair-accs).
__global__ __launch_bounds__(128) void nc_kernel(
    const float* __restrict__ x, const int* __restrict__ ei,
    const float* __restrict__ ang,
    const float* __restrict__ w0, const float* __restrict__ b0,
    const float* __restrict__ wh, const float* __restrict__ bh)
{
    __shared__ __align__(16) float sw0[33 * 16];
    __shared__ __align__(16) float sb0[16];
    __shared__ __align__(16) float swh[5 * 16 * 16];
    __shared__ __align__(16) float sbh[5 * 16];
    int t = threadIdx.x;
    for (int i = t; i < 33 * 16; i += 128) sw0[i] = w0[i];
    for (int i = t; i < 16;      i += 128) sb0[i] = b0[i];
    for (int i = t; i < 5 * 256; i += 128) swh[i] = wh[i];
    for (int i = t; i < 80;      i += 128) sbh[i] = bh[i];
    __syncthreads();

    int e = blockIdx.x * 128 + t;
    if (e >= NE) return;
    int s = ei[e];
    int d = ei[NE + e];

    float in[33];
    const float4* xd4 = (const float4*)(x + (size_t)d * CIN);
    const float4* xs4 = (const float4*)(x + (size_t)s * CIN);
    #pragma unroll
    for (int q = 0; q < 4; q++) {
        float4 v = xd4[q];
        in[q * 4 + 0] = v.x; in[q * 4 + 1] = v.y; in[q * 4 + 2] = v.z; in[q * 4 + 3] = v.w;
    }
    #pragma unroll
    for (int q = 0; q < 4; q++) {
        float4 v = xs4[q];
        in[16 + q * 4 + 0] = v.x; in[16 + q * 4 + 1] = v.y;
        in[16 + q * 4 + 2] = v.z; in[16 + q * 4 + 3] = v.w;
    }
    in[32] = ang[e];

    u64 acc[8];
    float h[16];
    #pragma unroll
    for (int jp = 0; jp < 8; jp++) acc[jp] = *(const u64*)(sb0 + 2 * jp);
    #pragma unroll
    for (int k = 0; k < 33; k++) {
        u64 vp = bcast2(in[k]);
        const float4* wr = (const float4*)(sw0 + k * 16);
        #pragma unroll
        for (int q = 0; q < 4; q++) {
            Q4 w; w.f4 = wr[q];
            acc[2 * q + 0] = fma2(vp, w.u[0], acc[2 * q + 0]);
            acc[2 * q + 1] = fma2(vp, w.u[1], acc[2 * q + 1]);
        }
    }
    #pragma unroll
    for (int jp = 0; jp < 8; jp++) {
        P2 p; p.u = acc[jp];
        h[2 * jp + 0] = fmaxf(p.f.x, 0.f);
        h[2 * jp + 1] = fmaxf(p.f.y, 0.f);
    }

    #pragma unroll 1
    for (int l = 0; l < NL; l++) {
        const float* wl = swh + l * 256;
        const float* bl = sbh + l * 16;
        #pragma unroll
        for (int jp = 0; jp < 8; jp++) acc[jp] = *(const u64*)(bl + 2 * jp);
        #pragma unroll
        for (int k = 0; k < 16; k++) {
            u64 vp = bcast2(h[k]);
            const float4* wr = (const float4*)(wl + k * 16);
            #pragma unroll
            for (int q = 0; q < 4; q++) {
                Q4 w; w.f4 = wr[q];
                acc[2 * q + 0] = fma2(vp, w.u[0], acc[2 * q + 0]);
                acc[2 * q + 1] = fma2(vp, w.u[1], acc[2 * q + 1]);
            }
        }
        #pragma unroll
        for (int jp = 0; jp < 8; jp++) {
            P2 p; p.u = acc[jp];
            h[2 * jp + 0] = fmaxf(p.f.x, 0.f);
            h[2 * jp + 1] = fmaxf(p.f.y, 0.f);
        }
    }

    #pragma unroll
    for (int j = 0; j < 16; j++) atomicAdd(&g_agg[(size_t)d * CIN + j], h[j]);
    atomicAdd(&g_cnt[d], 1.f);
}

// ---------------------------------------------------------------------------
__global__ void div_kernel(float* __restrict__ out) {
    int i = blockIdx.x * blockDim.x + threadIdx.x;
    if (i >= NN * CIN) return;
    float c = g_cnt[i / CIN];
    out[i] = g_agg[i] / fmaxf(c, 1.f);
}

// ---------------------------------------------------------------------------
// EdgeConv, f32x2-packed, fused dual-pass, 3-blocks/SM layout:
//  - h0 + accumulators in registers; h1 in a PRIVATE smem column (no syncs)
//  - input stash, h1, and combine weights share ONE 48x128 smem region
//    (stash dead after layer0; h1 dead after the fold)
//  - biases come from the constant bank (tiny traffic)
// smem/block = 75KB, regs capped at 170 -> 3 blocks (12 warps) per SM.
// IS_EC1=1: combine [fe, action](49) -> 48, out = g_ef1
// IS_EC1=0: combine [fe, ef1](96)   -> 1,  out = d_out
template <int IS_EC1>
__global__ __launch_bounds__(128, 3) void ec_kernel(
    const float* __restrict__ x, const int* __restrict__ ei,
    const float* __restrict__ extra,
    const float* __restrict__ w0, const float* __restrict__ wh,
    const float* __restrict__ wc, const float* __restrict__ bc,
    float* __restrict__ out, int sli)
{
    extern __shared__ float smem[];
    float* sw0 = smem;                 // 1536
    float* swh = sw0 + 1536;           // 11520
    float* reg = swh + 11520;          // 48*128: stash -> h1 -> wc/bc

    int t = threadIdx.x;
    for (int i = t; i < 1536;  i += 128) sw0[i] = w0[i];
    for (int i = t; i < 11520; i += 128) swh[i] = wh[i];

    int e = blockIdx.x * 128 + t;
    bool active = (e < NE);
    if (active) {
        int s = ei[e];
        int d = ei[NE + e];
        // stash rows 0..31 = [xd(16), xs(16)]  (pass1 = index XOR 16)
        const float4* a4 = (const float4*)(x + (size_t)d * CIN);
        const float4* b4 = (const float4*)(x + (size_t)s * CIN);
        #pragma unroll
        for (int q = 0; q < 4; q++) {
            float4 v = a4[q];
            reg[(q * 4 + 0) * 128 + t] = v.x; reg[(q * 4 + 1) * 128 + t] = v.y;
            reg[(q * 4 + 2) * 128 + t] = v.z; reg[(q * 4 + 3) * 128 + t] = v.w;
        }
        #pragma unroll
        for (int q = 0; q < 4; q++) {
            float4 v = b4[q];
            reg[(16 + q * 4 + 0) * 128 + t] = v.x; reg[(16 + q * 4 + 1) * 128 + t] = v.y;
            reg[(16 + q * 4 + 2) * 128 + t] = v.z; reg[(16 + q * 4 + 3) * 128 + t] = v.w;
        }
    }
    __syncthreads();   // weights + (private) stash ready

    float sq = 0.f;
    float h0[48];
    if (active) {
        u64 acc0[24], acc1[24];

        // ---- layer 0: 32 -> 48, fused passes, inputs from stash ----
        #pragma unroll
        for (int jp = 0; jp < 24; jp++) {
            u64 b = *(const u64*)(c_ec + C_B0 + 2 * jp);
            acc0[jp] = b; acc1[jp] = b;
        }
        #pragma unroll
        for (int k = 0; k < 32; k++) {
            u64 p0 = bcast2(reg[k * 128 + t]);
            u64 p1 = bcast2(reg[(k ^ 16) * 128 + t]);
            const float4* wr = (const float4*)(sw0 + k * 48);
            #pragma unroll
            for (int q = 0; q < 12; q++) {
                Q4 w; w.f4 = wr[q];
                acc0[2 * q + 0] = fma2(p0, w.u[0], acc0[2 * q + 0]);
                acc0[2 * q + 1] = fma2(p0, w.u[1], acc0[2 * q + 1]);
                acc1[2 * q + 0] = fma2(p1, w.u[0], acc1[2 * q + 0]);
                acc1[2 * q + 1] = fma2(p1, w.u[1], acc1[2 * q + 1]);
            }
        }
        // relu: h0 -> regs, h1 -> private smem column (overwrites stash rows)
        #pragma unroll
        for (int jp = 0; jp < 24; jp++) {
            P2 p; p.u = acc0[jp];
            h0[2 * jp + 0] = fmaxf(p.f.x, 0.f);
            h0[2 * jp + 1] = fmaxf(p.f.y, 0.f);
            P2 r; r.u = acc1[jp];
            reg[(2 * jp + 0) * 128 + t] = fmaxf(r.f.x, 0.f);
            reg[(2 * jp + 1) * 128 + t] = fmaxf(r.f.y, 0.f);
        }

        // ---- hidden layers: 48 -> 48, x5, fused passes ----
        #pragma unroll 1
        for (int l = 0; l < NL; l++) {
            const float* wl = swh + l * 2304;
            const float* bl = c_ec + C_BH + l * 48;
            #pragma unroll
            for (int jp = 0; jp < 24; jp++) {
                u64 b = *(const u64*)(bl + 2 * jp);
                acc0[jp] = b; acc1[jp] = b;
            }
            #pragma unroll
            for (int k = 0; k < 48; k++) {
                u64 p0 = bcast2(h0[k]);
                u64 p1 = bcast2(reg[k * 128 + t]);
                const float4* wr = (const float4*)(wl + k * 48);
                #pragma unroll
                for (int q = 0; q < 12; q++) {
                    Q4 w; w.f4 = wr[q];
                    acc0[2 * q + 0] = fma2(p0, w.u[0], acc0[2 * q + 0]);
                    acc0[2 * q + 1] = fma2(p0, w.u[1], acc0[2 * q + 1]);
                    acc1[2 * q + 0] = fma2(p1, w.u[0], acc1[2 * q + 0]);
                    acc1[2 * q + 1] = fma2(p1, w.u[1], acc1[2 * q + 1]);
                }
            }
            #pragma unroll
            for (int jp = 0; jp < 24; jp++) {
                P2 p; p.u = acc0[jp];
                h0[2 * jp + 0] = fmaxf(p.f.x, 0.f);
                h0[2 * jp + 1] = fmaxf(p.f.y, 0.f);
                P2 r; r.u = acc1[jp];
                reg[(2 * jp + 0) * 128 + t] = fmaxf(r.f.x, 0.f);
                reg[(2 * jp + 1) * 128 + t] = fmaxf(r.f.y, 0.f);
            }
        }

        // ---- side loss + fe (fe overwrites h0; h1 dead afterwards) ----
        #pragma unroll
        for (int j = 0; j < 48; j++) {
            float b = reg[j * 128 + t];
            float dl = h0[j] - b;
            sq += dl * dl;
            h0[j] = 0.5f * (h0[j] + b);
        }
    }

    // ---- combine weights into the (now free) reg region ----
    const int WCN = IS_EC1 ? 49 * 48 : 96;
    const int BCN = IS_EC1 ? 48 : 1;
    __syncthreads();   // all folds done; h1/stash region reusable
    for (int i = t; i < WCN; i += 128) reg[i] = wc[i];
    for (int i = t; i < BCN; i += 128) reg[WCN + i] = bc[i];
    __syncthreads();

    if (active) {
        const float* swc = reg;
        const float* sbc = reg + WCN;
        if (IS_EC1) {
            float aact = extra[e];
            u64 o[24];
            #pragma unroll
            for (int jp = 0; jp < 24; jp++) o[jp] = *(const u64*)(sbc + 2 * jp);
            {   // action row (row 48)
                u64 ap = bcast2(aact);
                const float4* wr = (const float4*)(swc + 48 * 48);
                #pragma unroll
                for (int q = 0; q < 12; q++) {
                    Q4 w; w.f4 = wr[q];
                    o[2 * q + 0] = fma2(ap, w.u[0], o[2 * q + 0]);
                    o[2 * q + 1] = fma2(ap, w.u[1], o[2 * q + 1]);
                }
            }
            #pragma unroll
            for (int k = 0; k < 48; k++) {
                u64 vp = bcast2(h0[k]);
                const float4* wr = (const float4*)(swc + k * 48);
                #pragma unroll
                for (int q = 0; q < 12; q++) {
                    Q4 w; w.f4 = wr[q];
                    o[2 * q + 0] = fma2(vp, w.u[0], o[2 * q + 0]);
                    o[2 * q + 1] = fma2(vp, w.u[1], o[2 * q + 1]);
                }
            }
            #pragma unroll
            for (int q = 0; q < 12; q++) {
                P2 p0; p0.u = o[2 * q + 0];
                P2 p1; p1.u = o[2 * q + 1];
                *(float4*)(out + (size_t)e * 48 + q * 4) =
                    make_float4(p0.f.x, p0.f.y, p1.f.x, p1.f.y);
            }
        } else {
            float o = sbc[0];
            #pragma unroll
            for (int k = 0; k < 48; k++) o += h0[k] * swc[k];
            const float4* ef = (const float4*)(extra + (size_t)e * 48);
            #pragma unroll
            for (int q = 0; q < 12; q++) {
                float4 v = ef[q];
                o += v.x * swc[48 + q * 4 + 0];
                o += v.y * swc[48 + q * 4 + 1];
                o += v.z * swc[48 + q * 4 + 2];
                o += v.w * swc[48 + q * 4 + 3];
            }
            out[e] = o;
        }
    }

    // side-loss reduction: warp shfl -> double atomic
    #pragma unroll
    for (int off = 16; off; off >>= 1)
        sq += __shfl_xor_sync(0xffffffffu, sq, off);
    if ((t & 31) == 0)
        atomicAdd(&g_sl[sli], (double)sq);
}

// ---------------------------------------------------------------------------
__global__ void fin_kernel(float* __restrict__ out) {
    double inv = 1.0 / ((double)NE * 48.0);
    out[NE] = (float)(0.5 * (g_sl[0] * inv + g_sl[1] * inv));
}

// ---------------------------------------------------------------------------
static void fill_const(const float* b0, const float* bh)
{
    cudaMemcpyToSymbolAsync(c_ec, b0, 48 * 4,  (size_t)C_B0 * 4, cudaMemcpyDeviceToDevice);
    cudaMemcpyToSymbolAsync(c_ec, bh, 240 * 4, (size_t)C_BH * 4, cudaMemcpyDeviceToDevice);
}

extern "C" void kernel_launch(void* const* d_in, const int* in_sizes, int n_in,
                              void* d_out, int out_size)
{
    const float* nf   = (const float*)d_in[0];
    const int*   ei   = (const int*)d_in[1];
    const float* ang  = (const float*)d_in[2];
    const float* act  = (const float*)d_in[4];
    const float* n1w0 = (const float*)d_in[5],  *n1b0 = (const float*)d_in[6];
    const float* n1wh = (const float*)d_in[7],  *n1bh = (const float*)d_in[8];
    const float* n2w0 = (const float*)d_in[9],  *n2b0 = (const float*)d_in[10];
    const float* n2wh = (const float*)d_in[11], *n2bh = (const float*)d_in[12];
    const float* e1w0 = (const float*)d_in[13], *e1b0 = (const float*)d_in[14];
    const float* e1wh = (const float*)d_in[15], *e1bh = (const float*)d_in[16];
    const float* e1wc = (const float*)d_in[17], *e1bc = (const float*)d_in[18];
    const float* e2w0 = (const float*)d_in[19], *e2b0 = (const float*)d_in[20];
    const float* e2wh = (const float*)d_in[21], *e2bh = (const float*)d_in[22];
    const float* e2wc = (const float*)d_in[23], *e2bc = (const float*)d_in[24];
    float* out = (float*)d_out;

    void *px1, *px2, *pef1;
    cudaGetSymbolAddress(&px1, g_x1);
    cudaGetSymbolAddress(&px2, g_x2);
    cudaGetSymbolAddress(&pef1, g_ef1);

    // smem/block: w0(1536) + wh(11520) + reg(48*128=6144) = 19200 f = 75KB
    size_t sh = (size_t)(1536 + 11520 + 48 * 128) * sizeof(float);
    cudaFuncSetAttribute(ec_kernel<1>, cudaFuncAttributeMaxDynamicSharedMemorySize, (int)sh);
    cudaFuncSetAttribute(ec_kernel<0>, cudaFuncAttributeMaxDynamicSharedMemorySize, (int)sh);
    cudaFuncSetAttribute(ec_kernel<1>, cudaFuncAttributePreferredSharedMemoryCarveout, 100);
    cudaFuncSetAttribute(ec_kernel<0>, cudaFuncAttributePreferredSharedMemoryCarveout, 100);

    // NodeConv1 -> x1
    zero_kernel<<<6250, 256>>>(0);
    nc_kernel<<<EB, 128>>>(nf, ei, ang, n1w0, n1b0, n1wh, n1bh);
    div_kernel<<<6250, 256>>>((float*)px1);
    // EdgeConv1 -> ef1 (E x 48), sl[0]
    fill_const(e1b0, e1bh);
    ec_kernel<1><<<EB, 128, sh>>>((const float*)px1, ei, act,
                                  e1w0, e1wh, e1wc, e1bc, (float*)pef1, 0);
    // NodeConv2 -> x2
    zero_kernel<<<6250, 256>>>(1);
    nc_kernel<<<EB, 128>>>((const float*)px1, ei, ang, n2w0, n2b0, n2wh, n2bh);
    div_kernel<<<6250, 256>>>((float*)px2);
    // EdgeConv2 -> out (E x 1), sl[1]
    fill_const(e2b0, e2bh);
    ec_kernel<0><<<EB, 128, sh>>>((const float*)px2, ei, (const float*)pef1,
                                  e2w0, e2wh, e2wc, e2bc, out, 1);
    if (out_size > NE) fin_kernel<<<1, 1>>>(out);
}